// round 6
// baseline (speedup 1.0000x reference)
#include <cuda_runtime.h>
#include <cstdint>

// Problem dims
#define B_  32
#define L_  2048
#define IN_ 512
#define H_  512
#define C_  1000
#define LH  (L_ * H_)        // 1048576
#define M_  (B_ * L_)        // 65536

// ---------------------------------------------------------------------------
// Generic fp32 GEMM:  C[M,N] = A[M,K] @ Bmat[N,K]^T + bias[N]   (unchanged)
// ---------------------------------------------------------------------------
#define BM 128
#define BN 128
#define BK 8
#define TM 8
#define TN 8

__global__ __launch_bounds__(256) void sgemm_bias_kernel(
    int M, int N, int K,
    const float* __restrict__ A,
    const float* __restrict__ Bmat,
    const float* __restrict__ bias,
    float* __restrict__ C)
{
    __shared__ float As[BK][BM];
    __shared__ float Bs[BK][BN];

    const int mTile = blockIdx.y * BM;
    const int nTile = blockIdx.x * BN;
    const int tid   = threadIdx.x;

    const int aRow = tid >> 1;
    const int aK   = (tid & 1) * 4;
    const int bRow = tid >> 1;
    const int bK   = (tid & 1) * 4;

    const int threadCol = tid & 15;
    const int threadRow = tid >> 4;

    float acc[TM][TN] = {};
    float regM[TM], regN[TN];

    for (int kb = 0; kb < K; kb += BK) {
        float4 a4 = *(const float4*)&A[(size_t)(mTile + aRow) * K + kb + aK];
        As[aK + 0][aRow] = a4.x;
        As[aK + 1][aRow] = a4.y;
        As[aK + 2][aRow] = a4.z;
        As[aK + 3][aRow] = a4.w;
        float4 b4 = make_float4(0.f, 0.f, 0.f, 0.f);
        if (nTile + bRow < N)
            b4 = *(const float4*)&Bmat[(size_t)(nTile + bRow) * K + kb + bK];
        Bs[bK + 0][bRow] = b4.x;
        Bs[bK + 1][bRow] = b4.y;
        Bs[bK + 2][bRow] = b4.z;
        Bs[bK + 3][bRow] = b4.w;
        __syncthreads();

        #pragma unroll
        for (int k = 0; k < BK; k++) {
            #pragma unroll
            for (int i = 0; i < TM; i++) regM[i] = As[k][threadRow * TM + i];
            #pragma unroll
            for (int j = 0; j < TN; j++) regN[j] = Bs[k][threadCol * TN + j];
            #pragma unroll
            for (int i = 0; i < TM; i++)
                #pragma unroll
                for (int j = 0; j < TN; j++)
                    acc[i][j] += regM[i] * regN[j];
        }
        __syncthreads();
    }

    #pragma unroll
    for (int i = 0; i < TM; i++) {
        const int row = mTile + threadRow * TM + i;
        #pragma unroll
        for (int j = 0; j < TN; j++) {
            const int col = nTile + threadCol * TN + j;
            if (col < N)
                C[(size_t)row * N + col] = acc[i][j] + bias[col];
        }
    }
}

// ---------------------------------------------------------------------------
// Cluster-local recurrence scan, bank-conflict-free smem layout.
//
//   16 clusters x 8 CTAs. Cluster cl owns batches {2cl, 2cl+1}; CTA rank r
//   owns columns [64r, 64r+64).
//
//   ws layout (weights, stationary): col stride 161 f4 (=644 floats, ==1 mod
//   32), K-quarter stride 40 f4 (=160 floats, ==8 mod 32). Lane (c8,q) load
//   at iter kk hits bank-quad (col + 8q + kk) mod 32 -> 32 distinct lanes,
//   conflict-free LDS.128, no address ALU in the loop.
//
//   hs layout (h, double buffered): batches packed as float2 (b0,b1);
//   quarter stride 72 f4 (=288 floats, ==8 mod 32) -> the four 8-lane
//   broadcast groups hit distinct bank-quads.
//
//   Per step each CTA broadcasts its 64 cols x 2 batches as packed b64
//   DSMEM stores to all 8 cluster CTAs; one barrier.cluster per step.
// ---------------------------------------------------------------------------
#define CLUSTER_N 8
#define SCAN_T    256

#define W_COL_STRIDE 644          // floats per col (4 quarters x 160 + 4 pad)
#define W_Q_STRIDE   160          // floats per K-quarter slot (128 data + 32 pad)
#define H_Q_STRIDE   288          // floats per quarter slot (256 data + 32 pad)
#define H_PHASE      (4 * H_Q_STRIDE)   // 1152 floats per phase

#define WS_FLOATS   (64 * W_COL_STRIDE)     // 41216
#define HS_FLOATS   (2 * H_PHASE)           // 2304
#define SMEM_FLOATS (WS_FLOATS + HS_FLOATS + 64)

__device__ __forceinline__ uint32_t smem_u32(const void* p) {
    uint32_t a;
    asm("{ .reg .u64 t; cvta.to.shared.u64 t, %1; cvt.u32.u64 %0, t; }"
        : "=r"(a) : "l"(p));
    return a;
}

__global__ void __cluster_dims__(CLUSTER_N, 1, 1) __launch_bounds__(SCAN_T)
rnn_scan_cluster_kernel(
    const float* __restrict__ hidden,
    const float* __restrict__ Wh,
    const float* __restrict__ bh,
    float* __restrict__ hn)
{
    extern __shared__ float sm[];
    float* ws  = sm;                      // [64 col][4 q][160]
    float* hs  = sm + WS_FLOATS;          // [2 phase][4 q][128 k x float2]
    float* bhs = hs + HS_FLOATS;          // [64]

    uint32_t rank;
    asm("mov.u32 %0, %%cluster_ctarank;" : "=r"(rank));
    const int cl = blockIdx.x >> 3;       // cluster id
    const int b0 = cl * 2;                // 2 batches per cluster
    const int c0 = (int)rank * 64;        // my 64 columns

    const int tid  = threadIdx.x;
    const int warp = tid >> 5;
    const int lane = tid & 31;
    const int c8   = lane & 7;
    const int q    = lane >> 3;           // K-quarter 0..3
    const int col  = warp * 8 + c8;       // 0..63
    const int cg   = c0 + col;            // global column

    // ---- load stationary Wh slice into padded layout ----
    for (int i = tid; i < 64 * 128; i += SCAN_T) {     // 8192 float4s
        const int r = i >> 7;
        const int k = (i & 127) * 4;
        *(float4*)&ws[r * W_COL_STRIDE + (k >> 7) * W_Q_STRIDE + (k & 127)] =
            *(const float4*)&Wh[(size_t)(c0 + r) * 512 + k];
    }
    if (tid < 64) bhs[tid] = bh[c0 + tid];

    // ---- initial h0 into phase-0 buffer, packed (b0,b1) ----
    for (int i = tid; i < 1024; i += SCAN_T) {
        const int b = i >> 9, k = i & 511;
        hs[(k >> 7) * H_Q_STRIDE + (k & 127) * 2 + b] =
            hidden[(size_t)(b0 + b) * LH + k];
    }
    __syncthreads();

    // ---- peer DSMEM base addresses of hs (symmetric layout) ----
    const uint32_t hs_local = smem_u32(hs);
    uint32_t peer_hs[CLUSTER_N];
    #pragma unroll
    for (int r = 0; r < CLUSTER_N; r++) {
        asm("mapa.shared::cluster.u32 %0, %1, %2;"
            : "=r"(peer_hs[r]) : "r"(hs_local), "r"(r));
    }

    const bool owner = (lane < 8);        // q==0 lanes hold reduced results
    const float bias_c = owner ? bhs[col] : 0.f;

    // writer offset pieces (owner lanes): quarter/slot of column cg
    const uint32_t wr_off_base = (uint32_t)(((cg >> 7) * H_Q_STRIDE +
                                             (cg & 127) * 2) * 4);

    // prefetch xp for t=0
    float xp0 = 0.f, xp1 = 0.f;
    if (owner) {
        xp0 = __ldg(&hn[(size_t)(b0 + 0) * LH + cg]);
        xp1 = __ldg(&hn[(size_t)(b0 + 1) * LH + cg]);
    }

    for (int t = 0; t < L_; t++) {
        const int p = t & 1;
        const float* wbase = &ws[col * W_COL_STRIDE + q * W_Q_STRIDE];
        const float* hbase = &hs[p * H_PHASE + q * H_Q_STRIDE];

        float a00 = 0.f, a01 = 0.f, a10 = 0.f, a11 = 0.f;
        #pragma unroll
        for (int i = 0; i < 32; i++) {
            const float4 w4 = *(const float4*)&wbase[i * 4];
            const float4 hA = *(const float4*)&hbase[i * 8];      // k, k+1
            const float4 hB = *(const float4*)&hbase[i * 8 + 4];  // k+2, k+3
            a00 += w4.x * hA.x;  a10 += w4.x * hA.y;
            a01 += w4.y * hA.z;  a11 += w4.y * hA.w;
            a00 += w4.z * hB.x;  a10 += w4.z * hB.y;
            a01 += w4.w * hB.z;  a11 += w4.w * hB.w;
        }
        float acc0 = a00 + a01;
        float acc1 = a10 + a11;
        // combine the 4 K-quarters (lanes L, L+8, L+16, L+24)
        acc0 += __shfl_down_sync(0xffffffffu, acc0, 16);
        acc1 += __shfl_down_sync(0xffffffffu, acc1, 16);
        acc0 += __shfl_down_sync(0xffffffffu, acc0, 8);
        acc1 += __shfl_down_sync(0xffffffffu, acc1, 8);

        if (owner) {
            const float hv0 = tanhf(acc0 + xp0 + bias_c);
            const float hv1 = tanhf(acc1 + xp1 + bias_c);

            // h_n output (also GEMM3 input)
            hn[(size_t)(b0 + 0) * LH + (size_t)t * H_ + cg] = hv0;
            hn[(size_t)(b0 + 1) * LH + (size_t)t * H_ + cg] = hv1;

            if (t != L_ - 1) {
                // one packed 8B store per peer into next-phase buffer
                unsigned long long pv;
                asm("mov.b64 %0, {%1, %2};" : "=l"(pv) : "f"(hv0), "f"(hv1));
                const uint32_t off = (uint32_t)((p ^ 1) * H_PHASE * 4) + wr_off_base;
                #pragma unroll
                for (int r = 0; r < CLUSTER_N; r++) {
                    asm volatile("st.shared::cluster.b64 [%0], %1;"
                                 :: "r"(peer_hs[r] + off), "l"(pv) : "memory");
                }
            }
        }

        if (t != L_ - 1) {
            // release my stores, then overlap xp prefetch with peers' arrival
            asm volatile("barrier.cluster.arrive.aligned;" ::: "memory");
            if (owner) {
                xp0 = __ldg(&hn[(size_t)(b0 + 0) * LH + (size_t)(t + 1) * H_ + cg]);
                xp1 = __ldg(&hn[(size_t)(b0 + 1) * LH + (size_t)(t + 1) * H_ + cg]);
            }
            asm volatile("barrier.cluster.wait.aligned;" ::: "memory");
        }
    }
}

// ---------------------------------------------------------------------------
// d_out layout: [ output (B,L,C) ][ h_n (B,L,H) ];  h_n doubles as x_proj.
// ---------------------------------------------------------------------------
extern "C" void kernel_launch(void* const* d_in, const int* in_sizes, int n_in,
                              void* d_out, int out_size)
{
    const float* inputs = (const float*)d_in[0];
    const float* hidden = (const float*)d_in[1];
    const float* Wi     = (const float*)d_in[2];
    const float* bi     = (const float*)d_in[3];
    const float* Wh     = (const float*)d_in[4];
    const float* bh     = (const float*)d_in[5];
    const float* Wo     = (const float*)d_in[6];
    const float* bo     = (const float*)d_in[7];

    float* out = (float*)d_out;
    float* hn  = out + (size_t)M_ * C_;

    // 1) x_proj = inputs @ Wi^T + bi  -> hn region
    {
        dim3 grid(H_ / BN, M_ / BM);
        sgemm_bias_kernel<<<grid, 256>>>(M_, H_, IN_, inputs, Wi, bi, hn);
    }

    // 2) cluster-local scan (1 launch, 2048 steps, no global sync)
    {
        const size_t smem_bytes = SMEM_FLOATS * sizeof(float);
        cudaFuncSetAttribute(rnn_scan_cluster_kernel,
                             cudaFuncAttributeMaxDynamicSharedMemorySize,
                             (int)smem_bytes);
        rnn_scan_cluster_kernel<<<16 * CLUSTER_N, SCAN_T, smem_bytes>>>(
            hidden, Wh, bh, hn);
    }

    // 3) output = h_n @ Wo^T + bo
    {
        dim3 grid((C_ + BN - 1) / BN, M_ / BM);
        sgemm_bias_kernel<<<grid, 256>>>(M_, C_, H_, hn, Wo, bo, out);
    }
}

// round 8
// speedup vs baseline: 1.1674x; 1.1674x over previous
#include <cuda_runtime.h>
#include <cstdint>

// Problem dims
#define B_  32
#define L_  2048
#define IN_ 512
#define H_  512
#define C_  1000
#define LH  (L_ * H_)        // 1048576
#define M_  (B_ * L_)        // 65536

// ---------------------------------------------------------------------------
// Generic fp32 GEMM:  C[M,N] = A[M,K] @ Bmat[N,K]^T + bias[N]   (unchanged)
// ---------------------------------------------------------------------------
#define BM 128
#define BN 128
#define BK 8
#define TM 8
#define TN 8

__global__ __launch_bounds__(256) void sgemm_bias_kernel(
    int M, int N, int K,
    const float* __restrict__ A,
    const float* __restrict__ Bmat,
    const float* __restrict__ bias,
    float* __restrict__ C)
{
    __shared__ float As[BK][BM];
    __shared__ float Bs[BK][BN];

    const int mTile = blockIdx.y * BM;
    const int nTile = blockIdx.x * BN;
    const int tid   = threadIdx.x;

    const int aRow = tid >> 1;
    const int aK   = (tid & 1) * 4;
    const int bRow = tid >> 1;
    const int bK   = (tid & 1) * 4;

    const int threadCol = tid & 15;
    const int threadRow = tid >> 4;

    float acc[TM][TN] = {};
    float regM[TM], regN[TN];

    for (int kb = 0; kb < K; kb += BK) {
        float4 a4 = *(const float4*)&A[(size_t)(mTile + aRow) * K + kb + aK];
        As[aK + 0][aRow] = a4.x;
        As[aK + 1][aRow] = a4.y;
        As[aK + 2][aRow] = a4.z;
        As[aK + 3][aRow] = a4.w;
        float4 b4 = make_float4(0.f, 0.f, 0.f, 0.f);
        if (nTile + bRow < N)
            b4 = *(const float4*)&Bmat[(size_t)(nTile + bRow) * K + kb + bK];
        Bs[bK + 0][bRow] = b4.x;
        Bs[bK + 1][bRow] = b4.y;
        Bs[bK + 2][bRow] = b4.z;
        Bs[bK + 3][bRow] = b4.w;
        __syncthreads();

        #pragma unroll
        for (int k = 0; k < BK; k++) {
            #pragma unroll
            for (int i = 0; i < TM; i++) regM[i] = As[k][threadRow * TM + i];
            #pragma unroll
            for (int j = 0; j < TN; j++) regN[j] = Bs[k][threadCol * TN + j];
            #pragma unroll
            for (int i = 0; i < TM; i++)
                #pragma unroll
                for (int j = 0; j < TN; j++)
                    acc[i][j] += regM[i] * regN[j];
        }
        __syncthreads();
    }

    #pragma unroll
    for (int i = 0; i < TM; i++) {
        const int row = mTile + threadRow * TM + i;
        #pragma unroll
        for (int j = 0; j < TN; j++) {
            const int col = nTile + threadCol * TN + j;
            if (col < N)
                C[(size_t)row * N + col] = acc[i][j] + bias[col];
        }
    }
}

// ---------------------------------------------------------------------------
// Cluster-local recurrence scan, mbarrier DATAFLOW (no cluster barrier).
//
//   16 clusters x 8 CTAs. Cluster cl owns batches {2cl, 2cl+1}; CTA rank r
//   owns columns [64r, 64r+64); Wh slice stationary in conflict-free padded
//   smem (R6 layout).
//
//   Per step, owner lanes push (hv0,hv1) packed b64 via
//   st.async.shared::cluster.mbarrier::complete_tx::bytes into every peer's
//   next-phase h buffer, accumulating tx on the peer's phase mbarrier
//   (expect 8 CTAs * 64 cols * 8B = 4096 B). Each CTA waits only on its OWN
//   mbarrier (try_wait.parity, HW sleep) -> no cluster-wide max barrier.
//
//   Safety of the 2-phase ring: a producer reaches step t+1 only after its
//   mbarrier confirmed all CTAs finished step-t stores, which occur strictly
//   after those CTAs finished reading phase (t&1). So overwriting phase
//   (t&1) with step-(t+1) results cannot race any reader.
// ---------------------------------------------------------------------------
#define CLUSTER_N 8
#define SCAN_T    256

#define W_COL_STRIDE 644          // floats per col (==1 mod 32 in f4 units)
#define W_Q_STRIDE   160          // K-quarter slot (==8 mod 32 in f4 units)
#define H_Q_STRIDE   288          // h quarter slot (==8 mod 32 in f4 units)
#define H_PHASE      (4 * H_Q_STRIDE)   // 1152 floats per phase

#define WS_FLOATS   (64 * W_COL_STRIDE)     // 41216
#define HS_FLOATS   (2 * H_PHASE)           // 2304
#define SMEM_FLOATS (WS_FLOATS + HS_FLOATS + 64 + 4)   // +4: two u64 mbarriers

#define TX_BYTES 4096u            // 8 CTAs * 64 cols * 8B per phase

__device__ __forceinline__ uint32_t smem_u32(const void* p) {
    uint32_t a;
    asm("{ .reg .u64 t; cvta.to.shared.u64 t, %1; cvt.u32.u64 %0, t; }"
        : "=r"(a) : "l"(p));
    return a;
}

__device__ __forceinline__ void mbar_wait_parity(uint32_t mbar, uint32_t parity) {
    uint32_t done;
    asm volatile(
        "{\n\t.reg .pred p;\n\t"
        "mbarrier.try_wait.parity.acquire.cta.shared::cta.b64 p, [%1], %2;\n\t"
        "selp.b32 %0, 1, 0, p;\n\t}"
        : "=r"(done) : "r"(mbar), "r"(parity) : "memory");
    if (!done) {
        asm volatile(
            "{\n\t.reg .pred P1;\n\t"
            "W_%=:\n\t"
            "mbarrier.try_wait.parity.acquire.cta.shared::cta.b64 P1, [%0], %1, 0x989680;\n\t"
            "@P1 bra.uni D_%=;\n\t"
            "bra.uni W_%=;\n\t"
            "D_%=:\n\t}"
            :: "r"(mbar), "r"(parity) : "memory");
    }
}

// tanh(x) = 1 - 2/(exp(2x)+1), via MUFU ex2 + rcp (~1e-7 rel, saturates to +-1)
__device__ __forceinline__ float fast_tanh(float x) {
    float e;
    asm("ex2.approx.f32 %0, %1;" : "=f"(e) : "f"(x * 2.8853900817779268f));
    float r;
    asm("rcp.approx.f32 %0, %1;" : "=f"(r) : "f"(e + 1.0f));
    return fmaf(-2.0f, r, 1.0f);
}

__global__ void __cluster_dims__(CLUSTER_N, 1, 1) __launch_bounds__(SCAN_T)
rnn_scan_cluster_kernel(
    const float* __restrict__ hidden,
    const float* __restrict__ Wh,
    const float* __restrict__ bh,
    float* __restrict__ hn)
{
    extern __shared__ float sm[];
    float* ws   = sm;                      // [64 col][4 q][160]
    float* hs   = sm + WS_FLOATS;          // [2 phase][4 q][128 k x float2]
    float* bhs  = hs + HS_FLOATS;          // [64]
    float* mbar = bhs + 64;                // 2 x u64 (byte off divisible by 8)

    uint32_t rank;
    asm("mov.u32 %0, %%cluster_ctarank;" : "=r"(rank));
    const int cl = blockIdx.x >> 3;
    const int b0 = cl * 2;
    const int c0 = (int)rank * 64;

    const int tid  = threadIdx.x;
    const int warp = tid >> 5;
    const int lane = tid & 31;
    const int c8   = lane & 7;
    const int q    = lane >> 3;
    const int col  = warp * 8 + c8;
    const int cg   = c0 + col;

    // ---- stationary Wh slice (padded conflict-free layout) ----
    for (int i = tid; i < 64 * 128; i += SCAN_T) {
        const int r = i >> 7;
        const int k = (i & 127) * 4;
        *(float4*)&ws[r * W_COL_STRIDE + (k >> 7) * W_Q_STRIDE + (k & 127)] =
            *(const float4*)&Wh[(size_t)(c0 + r) * 512 + k];
    }
    if (tid < 64) bhs[tid] = bh[c0 + tid];

    // ---- h0 into phase-0 buffer, packed (b0,b1) ----
    for (int i = tid; i < 1024; i += SCAN_T) {
        const int b = i >> 9, k = i & 511;
        hs[(k >> 7) * H_Q_STRIDE + (k & 127) * 2 + b] =
            hidden[(size_t)(b0 + b) * LH + k];
    }

    // ---- mbarriers: init count=1, pre-arm both phases' first uses ----
    const uint32_t mb_local = smem_u32(mbar);
    if (tid == 0) {
        asm volatile("mbarrier.init.shared.b64 [%0], 1;" :: "r"(mb_local) : "memory");
        asm volatile("mbarrier.init.shared.b64 [%0], 1;" :: "r"(mb_local + 8) : "memory");
        asm volatile("mbarrier.arrive.expect_tx.shared.b64 _, [%0], %1;"
                     :: "r"(mb_local), "r"(TX_BYTES) : "memory");      // use @ t=2
        asm volatile("mbarrier.arrive.expect_tx.shared.b64 _, [%0], %1;"
                     :: "r"(mb_local + 8), "r"(TX_BYTES) : "memory");  // use @ t=1
    }
    __syncthreads();
    // all CTAs' smem (h0 + mbarriers) ready before any peer st.async lands
    asm volatile("barrier.cluster.arrive.aligned;" ::: "memory");
    asm volatile("barrier.cluster.wait.aligned;"   ::: "memory");

    // ---- peer DSMEM addresses (symmetric layout) ----
    const uint32_t hs_local = smem_u32(hs);
    uint32_t peer_hs[CLUSTER_N], peer_mb[CLUSTER_N];
    #pragma unroll
    for (int r = 0; r < CLUSTER_N; r++) {
        asm("mapa.shared::cluster.u32 %0, %1, %2;"
            : "=r"(peer_hs[r]) : "r"(hs_local), "r"(r));
        asm("mapa.shared::cluster.u32 %0, %1, %2;"
            : "=r"(peer_mb[r]) : "r"(mb_local), "r"(r));
    }

    const bool owner = (lane < 8);
    const float bias_c = owner ? bhs[col] : 0.f;
    const uint32_t wr_off_base = (uint32_t)(((cg >> 7) * H_Q_STRIDE +
                                             (cg & 127) * 2) * 4);

    // prefetch xp for t=0
    float xp0 = 0.f, xp1 = 0.f;
    if (owner) {
        xp0 = __ldg(&hn[(size_t)(b0 + 0) * LH + cg]);
        xp1 = __ldg(&hn[(size_t)(b0 + 1) * LH + cg]);
    }

    uint32_t par0 = 0, par1 = 0;   // wait parity per phase mbarrier

    for (int t = 0; t < L_; t++) {
        const int p = t & 1;

        // ---- wait for this phase's h data (t=0 is local) ----
        if (t > 0) {
            const uint32_t mb = mb_local + 8u * (uint32_t)p;
            const uint32_t par = p ? par1 : par0;
            mbar_wait_parity(mb, par);
            if (p) par1 ^= 1; else par0 ^= 1;
            // re-arm this phase for its next use (step t+2)
            if (tid == 0 && t + 2 < L_) {
                asm volatile("mbarrier.arrive.expect_tx.shared.b64 _, [%0], %1;"
                             :: "r"(mb), "r"(TX_BYTES) : "memory");
            }
        }

        const float* wbase = &ws[col * W_COL_STRIDE + q * W_Q_STRIDE];
        const float* hbase = &hs[p * H_PHASE + q * H_Q_STRIDE];

        float a00 = 0.f, a01 = 0.f, a10 = 0.f, a11 = 0.f;
        #pragma unroll
        for (int i = 0; i < 32; i++) {
            const float4 w4 = *(const float4*)&wbase[i * 4];
            const float4 hA = *(const float4*)&hbase[i * 8];
            const float4 hB = *(const float4*)&hbase[i * 8 + 4];
            a00 += w4.x * hA.x;  a10 += w4.x * hA.y;
            a01 += w4.y * hA.z;  a11 += w4.y * hA.w;
            a00 += w4.z * hB.x;  a10 += w4.z * hB.y;
            a01 += w4.w * hB.z;  a11 += w4.w * hB.w;
        }
        float acc0 = a00 + a01;
        float acc1 = a10 + a11;
        acc0 += __shfl_down_sync(0xffffffffu, acc0, 16);
        acc1 += __shfl_down_sync(0xffffffffu, acc1, 16);
        acc0 += __shfl_down_sync(0xffffffffu, acc0, 8);
        acc1 += __shfl_down_sync(0xffffffffu, acc1, 8);

        if (owner) {
            const float hv0 = fast_tanh(acc0 + xp0 + bias_c);
            const float hv1 = fast_tanh(acc1 + xp1 + bias_c);

            if (t != L_ - 1) {
                // push to every peer's next-phase buffer + tx-signal its mbar
                unsigned long long pv;
                asm("mov.b64 %0, {%1, %2};" : "=l"(pv) : "f"(hv0), "f"(hv1));
                const uint32_t doff = (uint32_t)((p ^ 1) * H_PHASE * 4) + wr_off_base;
                const uint32_t moff = 8u * (uint32_t)(p ^ 1);
                #pragma unroll
                for (int r = 0; r < CLUSTER_N; r++) {
                    asm volatile(
                        "st.async.shared::cluster.mbarrier::complete_tx::bytes.b64 "
                        "[%0], %1, [%2];"
                        :: "r"(peer_hs[r] + doff), "l"(pv), "r"(peer_mb[r] + moff)
                        : "memory");
                }
            }

            // h_n output (also GEMM3 input)
            hn[(size_t)(b0 + 0) * LH + (size_t)t * H_ + cg] = hv0;
            hn[(size_t)(b0 + 1) * LH + (size_t)t * H_ + cg] = hv1;

            if (t != L_ - 1) {   // prefetch next xp; overlaps next wait
                xp0 = __ldg(&hn[(size_t)(b0 + 0) * LH + (size_t)(t + 1) * H_ + cg]);
                xp1 = __ldg(&hn[(size_t)(b0 + 1) * LH + (size_t)(t + 1) * H_ + cg]);
            }
        }
    }
}

// ---------------------------------------------------------------------------
// d_out layout: [ output (B,L,C) ][ h_n (B,L,H) ];  h_n doubles as x_proj.
// ---------------------------------------------------------------------------
extern "C" void kernel_launch(void* const* d_in, const int* in_sizes, int n_in,
                              void* d_out, int out_size)
{
    const float* inputs = (const float*)d_in[0];
    const float* hidden = (const float*)d_in[1];
    const float* Wi     = (const float*)d_in[2];
    const float* bi     = (const float*)d_in[3];
    const float* Wh     = (const float*)d_in[4];
    const float* bh     = (const float*)d_in[5];
    const float* Wo     = (const float*)d_in[6];
    const float* bo     = (const float*)d_in[7];

    float* out = (float*)d_out;
    float* hn  = out + (size_t)M_ * C_;

    // 1) x_proj = inputs @ Wi^T + bi  -> hn region
    {
        dim3 grid(H_ / BN, M_ / BM);
        sgemm_bias_kernel<<<grid, 256>>>(M_, H_, IN_, inputs, Wi, bi, hn);
    }

    // 2) cluster-local scan, mbarrier dataflow (1 launch, 2048 steps)
    {
        const size_t smem_bytes = SMEM_FLOATS * sizeof(float);
        cudaFuncSetAttribute(rnn_scan_cluster_kernel,
                             cudaFuncAttributeMaxDynamicSharedMemorySize,
                             (int)smem_bytes);
        rnn_scan_cluster_kernel<<<16 * CLUSTER_N, SCAN_T, smem_bytes>>>(
            hidden, Wh, bh, hn);
    }

    // 3) output = h_n @ Wo^T + bo
    {
        dim3 grid((C_ + BN - 1) / BN, M_ / BM);
        sgemm_bias_kernel<<<grid, 256>>>(M_, C_, H_, hn, Wo, bo, out);
    }
}